// round 11
// baseline (speedup 1.0000x reference)
#include <cuda_runtime.h>
#include <cuda_fp16.h>
#include <mma.h>
#include <math.h>

using namespace nvcuda;

// Problem dims
#define BB 16
#define NN 1024
#define LL 313
#define CC 768
#define HH 12
#define DHD 64
#define TT (NN + LL)       // 1337
#define TPAD 1344          // 21 * 64
#define MLPD 3072
#define NW 42              // TPAD/32 mask words per row
#define QKVD 2304
#define MTOK (BB * TT)     // 21392 token rows

// ---------------- scratch (device globals) -----------------------------------
__device__ float  g_xn[(size_t)BB * NN * CC];
__device__ __half g_tokens_h[(size_t)MTOK * CC];
__device__ __half g_qkv_h[(size_t)MTOK * QKVD];
__device__ __half g_attn_h[(size_t)BB * NN * CC];
__device__ float  g_x1[(size_t)BB * NN * CC];
__device__ __half g_h2_h[(size_t)BB * NN * CC];
__device__ __half g_act_h[(size_t)BB * NN * MLPD];
__device__ unsigned g_mbits[(size_t)BB * NN * NW];
__device__ __half g_wqkv_h[(size_t)CC * QKVD];
__device__ __half g_wp_h[(size_t)CC * CC];
__device__ __half g_w1_h[(size_t)CC * MLPD];
__device__ __half g_w2_h[(size_t)MLPD * CC];
__device__ float  g_bqkv[QKVD];

// ---------------- helpers -----------------------------------------------------
__device__ __forceinline__ void cp16(unsigned dst, const void* src) {
    asm volatile("cp.async.cg.shared.global [%0], [%1], 16;\n" :: "r"(dst), "l"(src));
}
__device__ __forceinline__ void cp16_pred(unsigned dst, const void* src, bool p) {
    int bytes = p ? 16 : 0;
    asm volatile("cp.async.cg.shared.global [%0], [%1], 16, %2;\n"
                 :: "r"(dst), "l"(src), "r"(bytes));
}
__device__ __forceinline__ int remap_row(int r, int doRemap) {
    return doRemap ? ((r >> 10) * TT + (r & 1023)) : r;   // NN == 1024
}

// ---------------- weight convert/pack -----------------------------------------
__global__ void wpack_kernel(const float* __restrict__ W, __half* __restrict__ dst,
                             int K, int N, int stride, int off)
{
    int i = blockIdx.x * 256 + threadIdx.x;
    if (i >= K * N) return;
    int k = i / N, n = i - k * N;
    dst[(size_t)k * stride + off + n] = __float2half(W[i]);
}

__global__ void biaspack_kernel(const float* __restrict__ bq,
                                const float* __restrict__ bk,
                                const float* __restrict__ bv)
{
    int i = blockIdx.x * 256 + threadIdx.x;
    if (i < CC) g_bqkv[i] = bq[i];
    else if (i < 2 * CC) g_bqkv[i] = bk[i - CC];
    else if (i < QKVD) g_bqkv[i] = bv[i - 2 * CC];
}

// ---------------- mask bit-packing --------------------------------------------
__global__ void mask_pack_kernel(const int* __restrict__ mask)
{
    int widx = blockIdx.x * 8 + (threadIdx.x >> 5);
    int lane = threadIdx.x & 31;
    if (widx >= BB * NN * NW) return;
    int w = widx % NW;
    int row = widx / NW;
    int gc = w * 32 + lane;
    int mval = (gc < TT) ? mask[(size_t)row * TT + gc] : 0;
    unsigned bits = __ballot_sync(~0u, mval != 0);
    if (lane == 0) g_mbits[widx] = bits;
}

// ---------------- LayerNorm 1 + concat ----------------------------------------
__global__ void ln1_concat_kernel(const float* __restrict__ x,
                                  const float* __restrict__ ce,
                                  const float* __restrict__ gam,
                                  const float* __restrict__ bet)
{
    int row = blockIdx.x;
    int b = row / TT;
    int t = row - b * TT;
    int tid = threadIdx.x;

    if (t >= NN) {
        const float* src = ce + ((size_t)b * LL + (t - NN)) * CC;
        __half* dst = g_tokens_h + (size_t)row * CC;
        for (int i = tid; i < CC; i += 256) dst[i] = __float2half(src[i]);
        return;
    }

    const float* src = x + ((size_t)b * NN + t) * CC;
    float v0 = src[tid], v1 = src[tid + 256], v2 = src[tid + 512];
    float s = v0 + v1 + v2;
    float s2 = v0 * v0 + v1 * v1 + v2 * v2;

    __shared__ float rs[8], rs2[8];
    int lane = tid & 31, warp = tid >> 5;
    #pragma unroll
    for (int o = 16; o; o >>= 1) {
        s  += __shfl_xor_sync(~0u, s, o);
        s2 += __shfl_xor_sync(~0u, s2, o);
    }
    if (lane == 0) { rs[warp] = s; rs2[warp] = s2; }
    __syncthreads();
    if (tid == 0) {
        float a = 0.f, c = 0.f;
        #pragma unroll
        for (int i = 0; i < 8; i++) { a += rs[i]; c += rs2[i]; }
        rs[0] = a; rs2[0] = c;
    }
    __syncthreads();
    float mu = rs[0] * (1.0f / CC);
    float var = rs2[0] * (1.0f / CC) - mu * mu;
    float rstd = rsqrtf(var + 1e-5f);

    float* oxn = g_xn + ((size_t)b * NN + t) * CC;
    __half* otk = g_tokens_h + (size_t)row * CC;
    int i = tid;
    float o = (v0 - mu) * rstd * gam[i] + bet[i]; oxn[i] = o; otk[i] = __float2half(o);
    i = tid + 256;
    o = (v1 - mu) * rstd * gam[i] + bet[i]; oxn[i] = o; otk[i] = __float2half(o);
    i = tid + 512;
    o = (v2 - mu) * rstd * gam[i] + bet[i]; oxn[i] = o; otk[i] = __float2half(o);
}

// ---------------- LayerNorm 2 (x1 -> h2 half) ---------------------------------
__global__ void ln2_kernel(const float* __restrict__ gam,
                           const float* __restrict__ bet)
{
    int row = blockIdx.x;
    int tid = threadIdx.x;
    const float* src = g_x1 + (size_t)row * CC;
    float v0 = src[tid], v1 = src[tid + 256], v2 = src[tid + 512];
    float s = v0 + v1 + v2;
    float s2 = v0 * v0 + v1 * v1 + v2 * v2;

    __shared__ float rs[8], rs2[8];
    int lane = tid & 31, warp = tid >> 5;
    #pragma unroll
    for (int o = 16; o; o >>= 1) {
        s  += __shfl_xor_sync(~0u, s, o);
        s2 += __shfl_xor_sync(~0u, s2, o);
    }
    if (lane == 0) { rs[warp] = s; rs2[warp] = s2; }
    __syncthreads();
    if (tid == 0) {
        float a = 0.f, c = 0.f;
        #pragma unroll
        for (int i = 0; i < 8; i++) { a += rs[i]; c += rs2[i]; }
        rs[0] = a; rs2[0] = c;
    }
    __syncthreads();
    float mu = rs[0] * (1.0f / CC);
    float var = rs2[0] * (1.0f / CC) - mu * mu;
    float rstd = rsqrtf(var + 1e-5f);

    __half* dst = g_h2_h + (size_t)row * CC;
    int i = tid;
    dst[i] = __float2half((v0 - mu) * rstd * gam[i] + bet[i]);
    i = tid + 256;
    dst[i] = __float2half((v1 - mu) * rstd * gam[i] + bet[i]);
    i = tid + 512;
    dst[i] = __float2half((v2 - mu) * rstd * gam[i] + bet[i]);
}

// ---------------- fp16 WMMA GEMM, 128x256 tiles, 4-stage cp.async -------------
// grid: (N/256, M-blocks)  -- n fastest for L2 reuse of A
#define GBM 128
#define GBN 256
#define GBK 32
#define LDA_H 40            // 32 + 8 pad (halves)
#define LDB_H 264           // 256 + 8 pad (halves)
#define ASTG (GBM * LDA_H)  // 5120 halves
#define BSTG (GBK * LDB_H)  // 8448 halves
#define STGB ((ASTG + BSTG) * 2)   // 27136 B
#define NSTG 4
#define GEMM_SMEM (NSTG * STGB)    // 108544 B
#define LDS_ 132
#define EPI_BIAS 0
#define EPI_GELU 1
#define EPI_ADD  2

__global__ void __launch_bounds__(256, 1)
gemm_h_kernel(const __half* __restrict__ A, const __half* __restrict__ W,
              const float* __restrict__ bias, const float* __restrict__ res,
              void* __restrict__ out, int M, int N, int K, int epi, int outHalf,
              int ldA, int ldW, int ldout, int rowRemap)
{
    extern __shared__ __align__(16) char smraw[];
    unsigned sbase = (unsigned)__cvta_generic_to_shared(smraw);

    int n0 = blockIdx.x * GBN;
    int m0 = blockIdx.y * GBM;
    int tid = threadIdx.x;
    int warp = tid >> 5;
    int wm = warp >> 2;   // 0..1 : 64-row group
    int wn = warp & 3;    // 0..3 : 64-col group

    wmma::fragment<wmma::accumulator, 16, 16, 16, float> acc[4][4];
    #pragma unroll
    for (int i = 0; i < 4; i++)
        #pragma unroll
        for (int j = 0; j < 4; j++)
            wmma::fill_fragment(acc[i][j], 0.0f);

    auto load_stage = [&](int c, int buf) {
        unsigned sa = sbase + buf * STGB;
        unsigned sb = sa + ASTG * 2;
        int k0 = c * GBK;
        // A: 128 rows x 4 chunks (8 halves) = 512 chunks
        #pragma unroll
        for (int p = 0; p < 2; p++) {
            int idx = tid + p * 256;
            int r = idx >> 2, cc = idx & 3;
            int gr = m0 + r; if (gr >= M) gr = M - 1;
            gr = remap_row(gr, rowRemap);
            cp16(sa + (r * LDA_H + cc * 8) * 2, A + (size_t)gr * ldA + k0 + cc * 8);
        }
        // B: 32 rows x 32 chunks = 1024 chunks
        #pragma unroll
        for (int p = 0; p < 4; p++) {
            int idx = tid + p * 256;
            int r = idx >> 5, cc = idx & 31;
            cp16(sb + (r * LDB_H + cc * 8) * 2, W + (size_t)(k0 + r) * ldW + n0 + cc * 8);
        }
        asm volatile("cp.async.commit_group;\n");
    };

    int KT = K / GBK;
    load_stage(0, 0);
    load_stage(1, 1);
    load_stage(2, 2);
    load_stage(3, 3);

    for (int kt = 0; kt < KT; kt++) {
        asm volatile("cp.async.wait_group 3;\n");
        __syncthreads();

        const __half* sA = (const __half*)(smraw + (kt & 3) * STGB);
        const __half* sB = sA + ASTG;
        #pragma unroll
        for (int kk = 0; kk < GBK; kk += 16) {
            wmma::fragment<wmma::matrix_a, 16, 16, 16, __half, wmma::row_major> af[4];
            wmma::fragment<wmma::matrix_b, 16, 16, 16, __half, wmma::row_major> bf[4];
            #pragma unroll
            for (int i = 0; i < 4; i++)
                wmma::load_matrix_sync(af[i], sA + (wm * 64 + i * 16) * LDA_H + kk, LDA_H);
            #pragma unroll
            for (int j = 0; j < 4; j++)
                wmma::load_matrix_sync(bf[j], sB + kk * LDB_H + wn * 64 + j * 16, LDB_H);
            #pragma unroll
            for (int i = 0; i < 4; i++)
                #pragma unroll
                for (int j = 0; j < 4; j++)
                    wmma::mma_sync(acc[i][j], af[i], bf[j], acc[i][j]);
        }
        __syncthreads();

        if (kt + 4 < KT) load_stage(kt + 4, (kt + 4) & 3);
        else asm volatile("cp.async.commit_group;\n");
    }

    // epilogue in two 128-col halves (fp32 smem stage reuses pipeline smem)
    float* stage = (float*)smraw;
    #pragma unroll
    for (int hh = 0; hh < 2; hh++) {
        __syncthreads();
        if ((wn >> 1) == hh) {
            #pragma unroll
            for (int i = 0; i < 4; i++)
                #pragma unroll
                for (int j = 0; j < 4; j++)
                    wmma::store_matrix_sync(stage + (wm * 64 + i * 16) * LDS_
                                            + (wn & 1) * 64 + j * 16,
                                            acc[i][j], LDS_, wmma::mem_row_major);
        }
        __syncthreads();

        int nh = n0 + hh * 128;
        for (int e = tid; e < 128 * 32; e += 256) {
            int r = e >> 5, c4 = e & 31;
            int gr = m0 + r, gc = nh + c4 * 4;
            if (gr < M) {
                int go = remap_row(gr, rowRemap);
                float4 v = *(float4*)(stage + r * LDS_ + c4 * 4);
                float4 bb = *(const float4*)(bias + gc);
                v.x += bb.x; v.y += bb.y; v.z += bb.z; v.w += bb.w;
                if (epi == EPI_GELU) {
                    v.x = 0.5f * v.x * (1.0f + erff(v.x * 0.70710678118654752f));
                    v.y = 0.5f * v.y * (1.0f + erff(v.y * 0.70710678118654752f));
                    v.z = 0.5f * v.z * (1.0f + erff(v.z * 0.70710678118654752f));
                    v.w = 0.5f * v.w * (1.0f + erff(v.w * 0.70710678118654752f));
                } else if (epi == EPI_ADD) {
                    float4 rr = *(const float4*)(res + (size_t)gr * ldout + gc);
                    v.x += rr.x; v.y += rr.y; v.z += rr.z; v.w += rr.w;
                }
                if (outHalf) {
                    __half2* oh = (__half2*)((__half*)out + (size_t)go * ldout + gc);
                    oh[0] = __floats2half2_rn(v.x, v.y);
                    oh[1] = __floats2half2_rn(v.z, v.w);
                } else {
                    *(float4*)((float*)out + (size_t)go * ldout + gc) = v;
                }
            }
        }
    }
}

// ---------------- Flash attention v2 (fp16 WMMA, O in registers) ---------------
#define AQ 64
#define LQH 72                     // half stride (Q,K,V,P)
#define LOF 68                     // float stride (S)
#define OFF_Q  0
#define OFF_K0 9216
#define OFF_V0 18432
#define OFF_K1 27648
#define OFF_V1 36864
#define OFF_P  46080
#define OFF_S  55296
#define OFF_M  72704
#define OFF_L  72960
#define OFF_SF 73216
#define ATTN_SMEM 73472

__global__ void __launch_bounds__(256, 2)
attn_kernel()
{
    extern __shared__ __align__(16) char smc[];
    unsigned sbase = (unsigned)__cvta_generic_to_shared(smc);
    __half* sQ = (__half*)(smc + OFF_Q);
    __half* sP = (__half*)(smc + OFF_P);
    float*  sS = (float*)(smc + OFF_S);
    float*  sM = (float*)(smc + OFF_M);
    float*  sL = (float*)(smc + OFF_L);
    float*  sSF = (float*)(smc + OFF_SF);

    int q0 = blockIdx.x * AQ;
    int h = blockIdx.y;
    int b = blockIdx.z;
    int tid = threadIdx.x;
    int warp = tid >> 5, lane = tid & 31;
    int wr = warp >> 1;   // 0..3 : 16-row group
    int wc = warp & 1;    // 0..1 : 32-col group

    if (tid < 64) { sM[tid] = -1e30f; sL[tid] = 0.f; }

    const __half* kb = g_qkv_h + (size_t)b * TT * QKVD + CC + h * DHD;
    const __half* vb = g_qkv_h + (size_t)b * TT * QKVD + 2 * CC + h * DHD;
    const unsigned* mb = g_mbits + ((size_t)b * NN + q0) * NW;

    auto load_kv = [&](int t0, int bi) {
        unsigned kB = sbase + (bi ? OFF_K1 : OFF_K0);
        unsigned vB = sbase + (bi ? OFF_V1 : OFF_V0);
        #pragma unroll
        for (int j = 0; j < 4; j++) {
            int e = tid + j * 256;              // 0..1023
            int isv = e >> 9;                   // 0=K, 1=V
            int ee = e & 511;
            int r = ee >> 3, c8 = ee & 7;
            int row = t0 + r;
            bool p = row < TT;
            int rs = p ? row : (TT - 1);
            const __half* src = (isv ? vb : kb) + (size_t)rs * QKVD + c8 * 8;
            cp16_pred((isv ? vB : kB) + (r * LQH + c8 * 8) * 2, src, p);
        }
        asm volatile("cp.async.commit_group;\n");
    };

    load_kv(0, 0);
    {
        const __half* qb = g_qkv_h + ((size_t)b * TT + q0) * QKVD + h * DHD;
        #pragma unroll
        for (int j = 0; j < 2; j++) {
            int e = tid + j * 256;
            int r = e >> 3, c8 = e & 7;
            float4 v = *(const float4*)(qb + (size_t)r * QKVD + c8 * 8);
            *(float4*)(sQ + r * LQH + c8 * 8) = v;
        }
    }
    asm volatile("cp.async.wait_group 0;\n");
    __syncthreads();

    wmma::fragment<wmma::accumulator, 16, 16, 16, float> oacc[2];
    wmma::fill_fragment(oacc[0], 0.0f);
    wmma::fill_fragment(oacc[1], 0.0f);

    const int NCH = TPAD / 64;   // 21
    for (int c = 0; c < NCH; c++) {
        int cur = c & 1;
        if (c + 1 < NCH) load_kv((c + 1) * 64, cur ^ 1);
        else asm volatile("cp.async.commit_group;\n");

        const __half* sK = (const __half*)(smc + (cur ? OFF_K1 : OFF_K0));
        const __half* sV = (const __half*)(smc + (cur ? OFF_V1 : OFF_V0));

        // S = Q @ K^T
        {
            wmma::fragment<wmma::accumulator, 16, 16, 16, float> sacc[2];
            wmma::fill_fragment(sacc[0], 0.0f);
            wmma::fill_fragment(sacc[1], 0.0f);
            #pragma unroll
            for (int kk = 0; kk < DHD; kk += 16) {
                wmma::fragment<wmma::matrix_a, 16, 16, 16, __half, wmma::row_major> af;
                wmma::fragment<wmma::matrix_b, 16, 16, 16, __half, wmma::col_major> bf;
                wmma::load_matrix_sync(af, sQ + (wr * 16) * LQH + kk, LQH);
                #pragma unroll
                for (int j = 0; j < 2; j++) {
                    wmma::load_matrix_sync(bf, sK + (wc * 32 + j * 16) * LQH + kk, LQH);
                    wmma::mma_sync(sacc[j], af, bf, sacc[j]);
                }
            }
            #pragma unroll
            for (int j = 0; j < 2; j++)
                wmma::store_matrix_sync(sS + (wr * 16) * LOF + wc * 32 + j * 16,
                                        sacc[j], LOF, wmma::mem_row_major);
        }
        __syncthreads();

        // online softmax (scale 0.125); P as half, sf per row
        #pragma unroll
        for (int i = 0; i < 8; i++) {
            int r = warp * 8 + i;
            float* srow = sS + r * LOF;
            unsigned w0 = mb[(size_t)r * NW + c * 2];
            unsigned w1 = mb[(size_t)r * NW + c * 2 + 1];
            bool v0 = (w0 >> lane) & 1u;
            bool v1 = (w1 >> lane) & 1u;
            float x0 = v0 ? srow[lane] * 0.125f : -1e30f;
            float x1 = v1 ? srow[lane + 32] * 0.125f : -1e30f;
            float cm = fmaxf(x0, x1);
            #pragma unroll
            for (int o = 16; o; o >>= 1) cm = fmaxf(cm, __shfl_xor_sync(~0u, cm, o));
            float m_old = sM[r];
            float m_new = fmaxf(m_old, cm);
            float p0 = v0 ? __expf(x0 - m_new) : 0.f;
            float p1 = v1 ? __expf(x1 - m_new) : 0.f;
            float ps = p0 + p1;
            #pragma unroll
            for (int o = 16; o; o >>= 1) ps += __shfl_xor_sync(~0u, ps, o);
            __half* prow = sP + r * LQH;
            prow[lane] = __float2half_rn(p0);
            prow[lane + 32] = __float2half_rn(p1);
            if (lane == 0) {
                float sf = __expf(m_old - m_new);
                sSF[r] = sf;
                sL[r] = sL[r] * sf + ps;
                sM[r] = m_new;
            }
        }
        __syncthreads();

        // rescale O fragments, then O += P @ V
        {
            float sf0 = sSF[wr * 16 + (lane >> 2)];
            float sf1 = sSF[wr * 16 + (lane >> 2) + 8];
            #pragma unroll
            for (int j = 0; j < 2; j++) {
                oacc[j].x[0] *= sf0; oacc[j].x[1] *= sf0;
                oacc[j].x[2] *= sf1; oacc[j].x[3] *= sf1;
                oacc[j].x[4] *= sf0; oacc[j].x[5] *= sf0;
                oacc[j].x[6] *= sf1; oacc[j].x[7] *= sf1;
            }
            #pragma unroll
            for (int kk = 0; kk < 64; kk += 16) {
                wmma::fragment<wmma::matrix_a, 16, 16, 16, __half, wmma::row_major> af;
                wmma::fragment<wmma::matrix_b, 16, 16, 16, __half, wmma::row_major> bf;
                wmma::load_matrix_sync(af, sP + (wr * 16) * LQH + kk, LQH);
                #pragma unroll
                for (int j = 0; j < 2; j++) {
                    wmma::load_matrix_sync(bf, sV + kk * LQH + wc * 32 + j * 16, LQH);
                    wmma::mma_sync(oacc[j], af, bf, oacc[j]);
                }
            }
        }

        asm volatile("cp.async.wait_group 0;\n");
        __syncthreads();
    }

    // finalize
    {
        float inv0 = 1.0f / sL[wr * 16 + (lane >> 2)];
        float inv1 = 1.0f / sL[wr * 16 + (lane >> 2) + 8];
        #pragma unroll
        for (int j = 0; j < 2; j++) {
            oacc[j].x[0] *= inv0; oacc[j].x[1] *= inv0;
            oacc[j].x[2] *= inv1; oacc[j].x[3] *= inv1;
            oacc[j].x[4] *= inv0; oacc[j].x[5] *= inv0;
            oacc[j].x[6] *= inv1; oacc[j].x[7] *= inv1;
        }
        #pragma unroll
        for (int j = 0; j < 2; j++)
            wmma::store_matrix_sync(sS + (wr * 16) * LOF + wc * 32 + j * 16,
                                    oacc[j], LOF, wmma::mem_row_major);
    }
    __syncthreads();

    __half* ob = g_attn_h + ((size_t)b * NN + q0) * CC + h * DHD;
    #pragma unroll
    for (int j = 0; j < 2; j++) {
        int e = tid + j * 256;
        int r = e >> 3, c8 = e & 7;
        const float* srow = sS + r * LOF + c8 * 8;
        __half2 h2[4];
        h2[0] = __floats2half2_rn(srow[0], srow[1]);
        h2[1] = __floats2half2_rn(srow[2], srow[3]);
        h2[2] = __floats2half2_rn(srow[4], srow[5]);
        h2[3] = __floats2half2_rn(srow[6], srow[7]);
        *(float4*)(ob + (size_t)r * CC + c8 * 8) = *(float4*)h2;
    }
}

// ---------------- launch -----------------------------------------------------
extern "C" void kernel_launch(void* const* d_in, const int* in_sizes, int n_in,
                              void* d_out, int out_size)
{
    const float* x    = (const float*)d_in[0];
    const float* ce   = (const float*)d_in[1];
    const int*   mask = (const int*)  d_in[2];
    const float* ln1g = (const float*)d_in[3];
    const float* ln1b = (const float*)d_in[4];
    const float* ln2g = (const float*)d_in[5];
    const float* ln2b = (const float*)d_in[6];
    const float* Wq   = (const float*)d_in[7];
    const float* bq   = (const float*)d_in[8];
    const float* Wk   = (const float*)d_in[9];
    const float* bk   = (const float*)d_in[10];
    const float* Wv   = (const float*)d_in[11];
    const float* bv   = (const float*)d_in[12];
    const float* Wp   = (const float*)d_in[13];
    const float* bp   = (const float*)d_in[14];
    const float* W1   = (const float*)d_in[15];
    const float* b1   = (const float*)d_in[16];
    const float* W2   = (const float*)d_in[17];
    const float* b2   = (const float*)d_in[18];
    float* out = (float*)d_out;

    float *p_xn, *p_x1, *p_bqkv;
    __half *p_tok, *p_qkv, *p_attn, *p_h2, *p_act, *p_wqkv, *p_wp, *p_w1, *p_w2;
    cudaGetSymbolAddress((void**)&p_xn,   g_xn);
    cudaGetSymbolAddress((void**)&p_tok,  g_tokens_h);
    cudaGetSymbolAddress((void**)&p_qkv,  g_qkv_h);
    cudaGetSymbolAddress((void**)&p_attn, g_attn_h);
    cudaGetSymbolAddress((void**)&p_x1,   g_x1);
    cudaGetSymbolAddress((void**)&p_h2,   g_h2_h);
    cudaGetSymbolAddress((void**)&p_act,  g_act_h);
    cudaGetSymbolAddress((void**)&p_wqkv, g_wqkv_h);
    cudaGetSymbolAddress((void**)&p_wp,   g_wp_h);
    cudaGetSymbolAddress((void**)&p_w1,   g_w1_h);
    cudaGetSymbolAddress((void**)&p_w2,   g_w2_h);
    cudaGetSymbolAddress((void**)&p_bqkv, g_bqkv);

    cudaFuncSetAttribute(gemm_h_kernel, cudaFuncAttributeMaxDynamicSharedMemorySize, GEMM_SMEM);
    cudaFuncSetAttribute(attn_kernel, cudaFuncAttributeMaxDynamicSharedMemorySize, ATTN_SMEM);

    int nCC = CC * CC, nCM = CC * MLPD;
    wpack_kernel<<<(nCC + 255) / 256, 256>>>(Wq, p_wqkv, CC, CC, QKVD, 0);
    wpack_kernel<<<(nCC + 255) / 256, 256>>>(Wk, p_wqkv, CC, CC, QKVD, CC);
    wpack_kernel<<<(nCC + 255) / 256, 256>>>(Wv, p_wqkv, CC, CC, QKVD, 2 * CC);
    wpack_kernel<<<(nCC + 255) / 256, 256>>>(Wp, p_wp, CC, CC, CC, 0);
    wpack_kernel<<<(nCM + 255) / 256, 256>>>(W1, p_w1, CC, MLPD, MLPD, 0);
    wpack_kernel<<<(nCM + 255) / 256, 256>>>(W2, p_w2, MLPD, CC, CC, 0);
    biaspack_kernel<<<(QKVD + 255) / 256, 256>>>(bq, bk, bv);

    mask_pack_kernel<<<(BB * NN * NW + 7) / 8, 256>>>(mask);
    ln1_concat_kernel<<<BB * TT, 256>>>(x, ce, ln1g, ln1b);

    // Q projection: only the B*N query rows (row-remapped into token space)
    gemm_h_kernel<<<dim3(CC / GBN, BB * NN / 128), 256, GEMM_SMEM>>>(
        p_tok, p_wqkv, p_bqkv, nullptr, p_qkv, BB * NN, CC, CC, EPI_BIAS, 1,
        CC, QKVD, QKVD, 1);

    // K|V projection: all token rows, output columns CC..3CC
    gemm_h_kernel<<<dim3((2 * CC) / GBN, (MTOK + 127) / 128), 256, GEMM_SMEM>>>(
        p_tok, p_wqkv + CC, p_bqkv + CC, nullptr, p_qkv + CC, MTOK, 2 * CC, CC,
        EPI_BIAS, 1, CC, QKVD, QKVD, 0);

    // attention (flash-2, fp16, O in registers)
    attn_kernel<<<dim3(NN / AQ, HH, BB), 256, ATTN_SMEM>>>();

    // proj + residual: x1 = xn + attn @ Wp + bp (fp32 out)
    gemm_h_kernel<<<dim3(CC / GBN, BB * NN / 128), 256, GEMM_SMEM>>>(
        p_attn, p_wp, bp, p_xn, p_x1, BB * NN, CC, CC, EPI_ADD, 0,
        CC, CC, CC, 0);

    ln2_kernel<<<BB * NN, 256>>>(ln2g, ln2b);

    // MLP
    gemm_h_kernel<<<dim3(MLPD / GBN, BB * NN / 128), 256, GEMM_SMEM>>>(
        p_h2, p_w1, b1, nullptr, p_act, BB * NN, MLPD, CC, EPI_GELU, 1,
        CC, MLPD, MLPD, 0);
    gemm_h_kernel<<<dim3(CC / GBN, BB * NN / 128), 256, GEMM_SMEM>>>(
        p_act, p_w2, b2, p_x1, out, BB * NN, CC, MLPD, EPI_ADD, 0,
        MLPD, CC, CC, 0);
}